// round 6
// baseline (speedup 1.0000x reference)
#include <cuda_runtime.h>
#include <math.h>
#include <stdint.h>

#define BATCH  2
#define SEQ    2048
#define DMODEL 2048
#define NH     16
#define NKV    4
#define DHEAD  128
#define REP    (NH / NKV)
#define ROWS   (BATCH * SEQ)     /* 4096 */
#define KVD    (NKV * DHEAD)     /* 512  */

#define BM 64
#define BN 64

// ---------------- scratch (static device arrays; no allocation) --------------
__device__ float g_q[(size_t)ROWS * DMODEL];
__device__ float g_k[(size_t)ROWS * KVD];
__device__ float g_v[(size_t)ROWS * KVD];
__device__ float g_qh[(size_t)ROWS * DMODEL];
__device__ float g_kh[(size_t)ROWS * KVD];
__device__ float g_vh[(size_t)ROWS * KVD];
__device__ float g_attn[(size_t)ROWS * DMODEL];

// ---------------- GEMM: C[M,N] = A[M,K] @ W[N,K]^T + bias --------------------
// 128x128 block tile, BK=16, 256 threads, 8x8 register tile per thread.
__global__ __launch_bounds__(256) void gemm_nt_bias(
    const float* __restrict__ A, const float* __restrict__ W,
    const float* __restrict__ bias, float* __restrict__ C,
    int M, int N, int K)
{
    __shared__ float As[16][132];
    __shared__ float Bs[16][132];

    const int tid = threadIdx.x;
    const int tx  = tid & 15;
    const int ty  = tid >> 4;
    const int m0  = blockIdx.y * 128;
    const int n0  = blockIdx.x * 128;
    const int lr  = tid >> 2;         // 0..63
    const int lc  = (tid & 3) << 2;   // 0,4,8,12

    float acc[8][8];
#pragma unroll
    for (int i = 0; i < 8; ++i)
#pragma unroll
        for (int j = 0; j < 8; ++j) acc[i][j] = 0.f;

    for (int k0 = 0; k0 < K; k0 += 16) {
#pragma unroll
        for (int h = 0; h < 2; ++h) {
            int row = lr + h * 64;
            float4 va = *reinterpret_cast<const float4*>(A + (size_t)(m0 + row) * K + k0 + lc);
            As[lc + 0][row] = va.x; As[lc + 1][row] = va.y;
            As[lc + 2][row] = va.z; As[lc + 3][row] = va.w;
            float4 vb = *reinterpret_cast<const float4*>(W + (size_t)(n0 + row) * K + k0 + lc);
            Bs[lc + 0][row] = vb.x; Bs[lc + 1][row] = vb.y;
            Bs[lc + 2][row] = vb.z; Bs[lc + 3][row] = vb.w;
        }
        __syncthreads();
#pragma unroll
        for (int kk = 0; kk < 16; ++kk) {
            float a[8], b[8];
            *reinterpret_cast<float4*>(a)     = *reinterpret_cast<const float4*>(&As[kk][ty * 8]);
            *reinterpret_cast<float4*>(a + 4) = *reinterpret_cast<const float4*>(&As[kk][ty * 8 + 4]);
            *reinterpret_cast<float4*>(b)     = *reinterpret_cast<const float4*>(&Bs[kk][tx * 8]);
            *reinterpret_cast<float4*>(b + 4) = *reinterpret_cast<const float4*>(&Bs[kk][tx * 8 + 4]);
#pragma unroll
            for (int i = 0; i < 8; ++i)
#pragma unroll
                for (int j = 0; j < 8; ++j)
                    acc[i][j] = fmaf(a[i], b[j], acc[i][j]);
        }
        __syncthreads();
    }

#pragma unroll
    for (int i = 0; i < 8; ++i) {
        int m = m0 + ty * 8 + i;
#pragma unroll
        for (int j = 0; j < 8; j += 4) {
            int n = n0 + tx * 8 + j;
            float4 v;
            v.x = acc[i][j + 0] + bias[n + 0];
            v.y = acc[i][j + 1] + bias[n + 1];
            v.z = acc[i][j + 2] + bias[n + 2];
            v.w = acc[i][j + 3] + bias[n + 3];
            *reinterpret_cast<float4*>(C + (size_t)m * N + n) = v;
        }
    }
}

// ---------------- RoPE + [B*S, H*DK] -> [B,H,S,DK] ---------------------------
__global__ void rope_heads(const float* __restrict__ src, float* __restrict__ dst,
                           const float* __restrict__ cosp, const float* __restrict__ sinp,
                           int nheads)
{
    size_t idx = (size_t)blockIdx.x * blockDim.x + threadIdx.x;   // pair index
    size_t total = (size_t)ROWS * nheads * (DHEAD / 2);
    if (idx >= total) return;
    int i = (int)(idx & 63);                   // pair idx within head (DK/2=64)
    int h = (int)((idx >> 6) % nheads);
    size_t row = idx / ((size_t)nheads * 64);  // b*SEQ + s
    int s = (int)(row & (SEQ - 1));
    int b = (int)(row >> 11);

    float2 t = *reinterpret_cast<const float2*>(src + (row * nheads + h) * DHEAD + 2 * i);
    float c  = cosp[s * 64 + i];
    float sn = sinp[s * 64 + i];
    float2 o;
    o.x = t.x * c - t.y * sn;
    o.y = t.x * sn + t.y * c;
    *reinterpret_cast<float2*>(dst + ((size_t)(b * nheads + h) * SEQ + s) * DHEAD + 2 * i) = o;
}

// ---------------- V: [B*S, HK*DK] -> [B,HK,S,DK] ------------------------------
__global__ void v_heads(const float* __restrict__ src, float* __restrict__ dst)
{
    size_t idx = (size_t)blockIdx.x * blockDim.x + threadIdx.x;
    if (idx >= (size_t)ROWS * KVD) return;
    int d = (int)(idx & 127);
    int h = (int)((idx >> 7) & 3);
    size_t row = idx >> 9;
    int s = (int)(row & (SEQ - 1));
    int b = (int)(row >> 11);
    dst[((size_t)(b * NKV + h) * SEQ + s) * DHEAD + d] = src[idx];
}

// ---------------- Flash attention (fp32, causal, GQA) -------------------------
// grid: (SEQ/BM, NH, BATCH), 256 threads.
// smem: Qs[128][68] (K-transposed, pre-scaled), Ks[128][68] (K-transposed),
//       Vs[64][132], Ps[64][68] (column-major: Ps[c][r]).
#define ATTN_SMEM_WORDS (128 * 68 + 128 * 68 + 64 * 132 + 64 * 68)
#define ATTN_SMEM_BYTES (ATTN_SMEM_WORDS * 4)

__global__ __launch_bounds__(256) void attn_kernel(
    const float* __restrict__ Q, const float* __restrict__ K,
    const float* __restrict__ V, float* __restrict__ O)
{
    extern __shared__ float sm[];
    float* Qs = sm;                  // [128][68]
    float* Ks = Qs + 128 * 68;       // [128][68]
    float* Vs = Ks + 128 * 68;       // [64][132]
    float* Ps = Vs + 64 * 132;       // [64][68] column-major: Ps[c*68 + r]

    const int tid = threadIdx.x;
    const int tx  = tid & 15;
    const int ty  = tid >> 4;
    const int qt  = blockIdx.x;
    const int h   = blockIdx.y;
    const int b   = blockIdx.z;
    const int g   = h / REP;

    const float* Qp = Q + ((size_t)(b * NH  + h) * SEQ + (size_t)qt * BM) * DHEAD;
    const float* Kp = K + ((size_t)(b * NKV + g) * SEQ) * DHEAD;
    const float* Vp = V + ((size_t)(b * NKV + g) * SEQ) * DHEAD;

    const float scale = 0.08838834764831845f;  // 1/sqrt(128)

    // Load Q tile, transposed into Qs[d][r], pre-scaled.
    for (int idx = tid; idx < BM * DHEAD; idx += 256) {
        int r = idx >> 7;
        int d = idx & 127;
        Qs[d * 68 + r] = Qp[idx] * scale;
    }

    const int r0  = ty * 4;   // S/P/O rows owned by this thread
    const int c0  = tx * 4;   // S/P cols
    const int cc0 = tx * 8;   // O cols

    float o[4][8];
#pragma unroll
    for (int i = 0; i < 4; ++i)
#pragma unroll
        for (int j = 0; j < 8; ++j) o[i][j] = 0.f;
    float mrow[4] = {-INFINITY, -INFINITY, -INFINITY, -INFINITY};
    float lrow[4] = {0.f, 0.f, 0.f, 0.f};

    for (int kt = 0; kt <= qt; ++kt) {
        // Load K (transposed) and V tiles.
        for (int idx = tid; idx < BN * DHEAD; idx += 256) {
            int c = idx >> 7;
            int d = idx & 127;
            size_t goff = (size_t)kt * BN * DHEAD + idx;
            Ks[d * 68 + c]  = Kp[goff];
            Vs[c * 132 + d] = Vp[goff];
        }
        __syncthreads();

        // S = Q K^T  (4x4 per thread)
        float s[4][4];
#pragma unroll
        for (int i = 0; i < 4; ++i)
#pragma unroll
            for (int j = 0; j < 4; ++j) s[i][j] = 0.f;

#pragma unroll 4
        for (int d = 0; d < DHEAD; ++d) {
            float a[4], bb[4];
            *reinterpret_cast<float4*>(a)  = *reinterpret_cast<const float4*>(Qs + d * 68 + r0);
            *reinterpret_cast<float4*>(bb) = *reinterpret_cast<const float4*>(Ks + d * 68 + c0);
#pragma unroll
            for (int i = 0; i < 4; ++i)
#pragma unroll
                for (int j = 0; j < 4; ++j)
                    s[i][j] = fmaf(a[i], bb[j], s[i][j]);
        }

        // causal mask (only the diagonal tile can violate causality)
        if (kt == qt) {
#pragma unroll
            for (int i = 0; i < 4; ++i)
#pragma unroll
                for (int j = 0; j < 4; ++j)
                    if (c0 + j > r0 + i) s[i][j] = -INFINITY;
        }

        // row max (across tx group of 16 lanes)
        float mt[4];
#pragma unroll
        for (int i = 0; i < 4; ++i) {
            float m = fmaxf(fmaxf(s[i][0], s[i][1]), fmaxf(s[i][2], s[i][3]));
#pragma unroll
            for (int off = 8; off; off >>= 1)
                m = fmaxf(m, __shfl_xor_sync(0xffffffffu, m, off));
            mt[i] = m;
        }

        float al[4];
#pragma unroll
        for (int i = 0; i < 4; ++i) {
            float mn = fmaxf(mrow[i], mt[i]);
            al[i]    = __expf(mrow[i] - mn);
            mrow[i]  = mn;
        }

        // p = exp(s - m); row sums; write P column-major
#pragma unroll
        for (int i = 0; i < 4; ++i) {
            float sum = 0.f;
#pragma unroll
            for (int j = 0; j < 4; ++j) {
                float p = __expf(s[i][j] - mrow[i]);
                s[i][j] = p;
                sum += p;
            }
#pragma unroll
            for (int off = 8; off; off >>= 1)
                sum += __shfl_xor_sync(0xffffffffu, sum, off);
            lrow[i] = lrow[i] * al[i] + sum;
#pragma unroll
            for (int j = 0; j < 8; ++j) o[i][j] *= al[i];
        }
#pragma unroll
        for (int j = 0; j < 4; ++j) {
            float4 w = make_float4(s[0][j], s[1][j], s[2][j], s[3][j]);
            *reinterpret_cast<float4*>(Ps + (c0 + j) * 68 + r0) = w;
        }
        __syncthreads();

        // O += P V   (4 rows x 8 cols per thread)
#pragma unroll 2
        for (int kk = 0; kk < BN; ++kk) {
            float4 pw = *reinterpret_cast<const float4*>(Ps + kk * 68 + r0);
            float p4[4] = {pw.x, pw.y, pw.z, pw.w};
            float4 v0 = *reinterpret_cast<const float4*>(Vs + kk * 132 + cc0);
            float4 v1 = *reinterpret_cast<const float4*>(Vs + kk * 132 + cc0 + 4);
            float vv[8] = {v0.x, v0.y, v0.z, v0.w, v1.x, v1.y, v1.z, v1.w};
#pragma unroll
            for (int i = 0; i < 4; ++i)
#pragma unroll
                for (int j = 0; j < 8; ++j)
                    o[i][j] = fmaf(p4[i], vv[j], o[i][j]);
        }
        __syncthreads();
    }

    // epilogue: normalize and write to g_attn [B*S, H*DK]
    size_t qrow_base = (size_t)b * SEQ + (size_t)qt * BM;
#pragma unroll
    for (int i = 0; i < 4; ++i) {
        float inv = 1.f / lrow[i];
        size_t base = (qrow_base + r0 + i) * DMODEL + (size_t)h * DHEAD + cc0;
        float4 w0 = make_float4(o[i][0] * inv, o[i][1] * inv, o[i][2] * inv, o[i][3] * inv);
        float4 w1 = make_float4(o[i][4] * inv, o[i][5] * inv, o[i][6] * inv, o[i][7] * inv);
        *reinterpret_cast<float4*>(O + base)     = w0;
        *reinterpret_cast<float4*>(O + base + 4) = w1;
    }
}

// ---------------- launch ------------------------------------------------------
extern "C" void kernel_launch(void* const* d_in, const int* in_sizes, int n_in,
                              void* d_out, int out_size)
{
    const float* x    = (const float*)d_in[0];
    const float* fcos = (const float*)d_in[1];
    const float* fsin = (const float*)d_in[2];
    const float* wq_w = (const float*)d_in[3];
    const float* wq_b = (const float*)d_in[4];
    const float* wk_w = (const float*)d_in[5];
    const float* wk_b = (const float*)d_in[6];
    const float* wv_w = (const float*)d_in[7];
    const float* wv_b = (const float*)d_in[8];
    const float* wo_w = (const float*)d_in[9];
    const float* wo_b = (const float*)d_in[10];
    float* out = (float*)d_out;

    static float *q = nullptr, *k, *v, *qh, *kh, *vh, *attn;
    static bool init_done = false;
    if (!init_done) {
        cudaGetSymbolAddress((void**)&q,    g_q);
        cudaGetSymbolAddress((void**)&k,    g_k);
        cudaGetSymbolAddress((void**)&v,    g_v);
        cudaGetSymbolAddress((void**)&qh,   g_qh);
        cudaGetSymbolAddress((void**)&kh,   g_kh);
        cudaGetSymbolAddress((void**)&vh,   g_vh);
        cudaGetSymbolAddress((void**)&attn, g_attn);
        cudaFuncSetAttribute(attn_kernel, cudaFuncAttributeMaxDynamicSharedMemorySize,
                             ATTN_SMEM_BYTES);
        init_done = true;
    }

    dim3 blk(256);

    // QKV projections
    gemm_nt_bias<<<dim3(DMODEL / 128, ROWS / 128), blk>>>(x, wq_w, wq_b, q, ROWS, DMODEL, DMODEL);
    gemm_nt_bias<<<dim3(KVD    / 128, ROWS / 128), blk>>>(x, wk_w, wk_b, k, ROWS, KVD,    DMODEL);
    gemm_nt_bias<<<dim3(KVD    / 128, ROWS / 128), blk>>>(x, wv_w, wv_b, v, ROWS, KVD,    DMODEL);

    // RoPE + head rearrangement
    {
        size_t totq = (size_t)ROWS * NH  * (DHEAD / 2);
        size_t totk = (size_t)ROWS * NKV * (DHEAD / 2);
        size_t totv = (size_t)ROWS * KVD;
        rope_heads<<<(unsigned)((totq + 255) / 256), 256>>>(q, qh, fcos, fsin, NH);
        rope_heads<<<(unsigned)((totk + 255) / 256), 256>>>(k, kh, fcos, fsin, NKV);
        v_heads  <<<(unsigned)((totv + 255) / 256), 256>>>(v, vh);
    }

    // causal GQA attention
    attn_kernel<<<dim3(SEQ / BM, NH, BATCH), blk, ATTN_SMEM_BYTES>>>(qh, kh, vh, attn);

    // output projection -> d_out
    gemm_nt_bias<<<dim3(DMODEL / 128, ROWS / 128), blk>>>(attn, wo_w, wo_b, out, ROWS, DMODEL, DMODEL);
}

// round 7
// speedup vs baseline: 1.0018x; 1.0018x over previous
#include <cuda_runtime.h>
#include <math.h>
#include <stdint.h>

#define BATCH  2
#define SEQ    2048
#define DMODEL 2048
#define NH     16
#define NKV    4
#define DHEAD  128
#define REP    (NH / NKV)
#define ROWS   (BATCH * SEQ)     /* 4096 */
#define KVD    (NKV * DHEAD)     /* 512  */

#define BM 64
#define BN 64

// ---------------- scratch (static device arrays; no allocation) --------------
__device__ float g_q[(size_t)ROWS * DMODEL];
__device__ float g_k[(size_t)ROWS * KVD];
__device__ float g_v[(size_t)ROWS * KVD];
__device__ float g_qh[(size_t)ROWS * DMODEL];
__device__ float g_kh[(size_t)ROWS * KVD];
__device__ float g_vh[(size_t)ROWS * KVD];
__device__ float g_attn[(size_t)ROWS * DMODEL];

// ---------------- GEMM: C[M,N] = A[M,K] @ W[N,K]^T + bias --------------------
// 128x128 block tile, BK=16, 256 threads, 8x8 register tile per thread.
__global__ __launch_bounds__(256) void gemm_nt_bias(
    const float* __restrict__ A, const float* __restrict__ W,
    const float* __restrict__ bias, float* __restrict__ C,
    int M, int N, int K)
{
    __shared__ float As[16][132];
    __shared__ float Bs[16][132];

    const int tid = threadIdx.x;
    const int tx  = tid & 15;
    const int ty  = tid >> 4;
    const int m0  = blockIdx.y * 128;
    const int n0  = blockIdx.x * 128;
    const int lr  = tid >> 2;         // 0..63
    const int lc  = (tid & 3) << 2;   // 0,4,8,12

    float acc[8][8];
#pragma unroll
    for (int i = 0; i < 8; ++i)
#pragma unroll
        for (int j = 0; j < 8; ++j) acc[i][j] = 0.f;

    for (int k0 = 0; k0 < K; k0 += 16) {
#pragma unroll
        for (int h = 0; h < 2; ++h) {
            int row = lr + h * 64;
            float4 va = *reinterpret_cast<const float4*>(A + (size_t)(m0 + row) * K + k0 + lc);
            As[lc + 0][row] = va.x; As[lc + 1][row] = va.y;
            As[lc + 2][row] = va.z; As[lc + 3][row] = va.w;
            float4 vb = *reinterpret_cast<const float4*>(W + (size_t)(n0 + row) * K + k0 + lc);
            Bs[lc + 0][row] = vb.x; Bs[lc + 1][row] = vb.y;
            Bs[lc + 2][row] = vb.z; Bs[lc + 3][row] = vb.w;
        }
        __syncthreads();
#pragma unroll
        for (int kk = 0; kk < 16; ++kk) {
            float a[8], b[8];
            *reinterpret_cast<float4*>(a)     = *reinterpret_cast<const float4*>(&As[kk][ty * 8]);
            *reinterpret_cast<float4*>(a + 4) = *reinterpret_cast<const float4*>(&As[kk][ty * 8 + 4]);
            *reinterpret_cast<float4*>(b)     = *reinterpret_cast<const float4*>(&Bs[kk][tx * 8]);
            *reinterpret_cast<float4*>(b + 4) = *reinterpret_cast<const float4*>(&Bs[kk][tx * 8 + 4]);
#pragma unroll
            for (int i = 0; i < 8; ++i)
#pragma unroll
                for (int j = 0; j < 8; ++j)
                    acc[i][j] = fmaf(a[i], b[j], acc[i][j]);
        }
        __syncthreads();
    }

#pragma unroll
    for (int i = 0; i < 8; ++i) {
        int m = m0 + ty * 8 + i;
#pragma unroll
        for (int j = 0; j < 8; j += 4) {
            int n = n0 + tx * 8 + j;
            float4 v;
            v.x = acc[i][j + 0] + bias[n + 0];
            v.y = acc[i][j + 1] + bias[n + 1];
            v.z = acc[i][j + 2] + bias[n + 2];
            v.w = acc[i][j + 3] + bias[n + 3];
            *reinterpret_cast<float4*>(C + (size_t)m * N + n) = v;
        }
    }
}

// ---------------- RoPE + [B*S, H*DK] -> [B,H,S,DK] ---------------------------
__global__ void rope_heads(const float* __restrict__ src, float* __restrict__ dst,
                           const float* __restrict__ cosp, const float* __restrict__ sinp,
                           int nheads)
{
    size_t idx = (size_t)blockIdx.x * blockDim.x + threadIdx.x;   // pair index
    size_t total = (size_t)ROWS * nheads * (DHEAD / 2);
    if (idx >= total) return;
    int i = (int)(idx & 63);                   // pair idx within head (DK/2=64)
    int h = (int)((idx >> 6) % nheads);
    size_t row = idx / ((size_t)nheads * 64);  // b*SEQ + s
    int s = (int)(row & (SEQ - 1));
    int b = (int)(row >> 11);

    float2 t = *reinterpret_cast<const float2*>(src + (row * nheads + h) * DHEAD + 2 * i);
    float c  = cosp[s * 64 + i];
    float sn = sinp[s * 64 + i];
    float2 o;
    o.x = t.x * c - t.y * sn;
    o.y = t.x * sn + t.y * c;
    *reinterpret_cast<float2*>(dst + ((size_t)(b * nheads + h) * SEQ + s) * DHEAD + 2 * i) = o;
}

// ---------------- V: [B*S, HK*DK] -> [B,HK,S,DK] ------------------------------
__global__ void v_heads(const float* __restrict__ src, float* __restrict__ dst)
{
    size_t idx = (size_t)blockIdx.x * blockDim.x + threadIdx.x;
    if (idx >= (size_t)ROWS * KVD) return;
    int d = (int)(idx & 127);
    int h = (int)((idx >> 7) & 3);
    size_t row = idx >> 9;
    int s = (int)(row & (SEQ - 1));
    int b = (int)(row >> 11);
    dst[((size_t)(b * NKV + h) * SEQ + s) * DHEAD + d] = src[idx];
}

// ---------------- Flash attention (fp32, causal, GQA) -------------------------
// grid: (SEQ/BM, NH, BATCH), 256 threads.
// smem: Qs[128][68] (K-transposed, pre-scaled), Ks[128][68] (K-transposed),
//       Vs[64][132], Ps[64][68] (column-major: Ps[c][r]).
#define ATTN_SMEM_WORDS (128 * 68 + 128 * 68 + 64 * 132 + 64 * 68)
#define ATTN_SMEM_BYTES (ATTN_SMEM_WORDS * 4)

__global__ __launch_bounds__(256) void attn_kernel(
    const float* __restrict__ Q, const float* __restrict__ K,
    const float* __restrict__ V, float* __restrict__ O)
{
    extern __shared__ float sm[];
    float* Qs = sm;                  // [128][68]
    float* Ks = Qs + 128 * 68;       // [128][68]
    float* Vs = Ks + 128 * 68;       // [64][132]
    float* Ps = Vs + 64 * 132;       // [64][68] column-major: Ps[c*68 + r]

    const int tid = threadIdx.x;
    const int tx  = tid & 15;
    const int ty  = tid >> 4;
    const int qt  = blockIdx.x;
    const int h   = blockIdx.y;
    const int b   = blockIdx.z;
    const int g   = h / REP;

    const float* Qp = Q + ((size_t)(b * NH  + h) * SEQ + (size_t)qt * BM) * DHEAD;
    const float* Kp = K + ((size_t)(b * NKV + g) * SEQ) * DHEAD;
    const float* Vp = V + ((size_t)(b * NKV + g) * SEQ) * DHEAD;

    const float scale = 0.08838834764831845f;  // 1/sqrt(128)

    // Load Q tile, transposed into Qs[d][r], pre-scaled.
    for (int idx = tid; idx < BM * DHEAD; idx += 256) {
        int r = idx >> 7;
        int d = idx & 127;
        Qs[d * 68 + r] = Qp[idx] * scale;
    }

    const int r0  = ty * 4;   // S/P/O rows owned by this thread
    const int c0  = tx * 4;   // S/P cols
    const int cc0 = tx * 8;   // O cols

    float o[4][8];
#pragma unroll
    for (int i = 0; i < 4; ++i)
#pragma unroll
        for (int j = 0; j < 8; ++j) o[i][j] = 0.f;
    float mrow[4] = {-INFINITY, -INFINITY, -INFINITY, -INFINITY};
    float lrow[4] = {0.f, 0.f, 0.f, 0.f};

    for (int kt = 0; kt <= qt; ++kt) {
        // Load K (transposed) and V tiles.
        for (int idx = tid; idx < BN * DHEAD; idx += 256) {
            int c = idx >> 7;
            int d = idx & 127;
            size_t goff = (size_t)kt * BN * DHEAD + idx;
            Ks[d * 68 + c]  = Kp[goff];
            Vs[c * 132 + d] = Vp[goff];
        }
        __syncthreads();

        // S = Q K^T  (4x4 per thread)
        float s[4][4];
#pragma unroll
        for (int i = 0; i < 4; ++i)
#pragma unroll
            for (int j = 0; j < 4; ++j) s[i][j] = 0.f;

#pragma unroll 4
        for (int d = 0; d < DHEAD; ++d) {
            float a[4], bb[4];
            *reinterpret_cast<float4*>(a)  = *reinterpret_cast<const float4*>(Qs + d * 68 + r0);
            *reinterpret_cast<float4*>(bb) = *reinterpret_cast<const float4*>(Ks + d * 68 + c0);
#pragma unroll
            for (int i = 0; i < 4; ++i)
#pragma unroll
                for (int j = 0; j < 4; ++j)
                    s[i][j] = fmaf(a[i], bb[j], s[i][j]);
        }

        // causal mask (only the diagonal tile can violate causality)
        if (kt == qt) {
#pragma unroll
            for (int i = 0; i < 4; ++i)
#pragma unroll
                for (int j = 0; j < 4; ++j)
                    if (c0 + j > r0 + i) s[i][j] = -INFINITY;
        }

        // row max (across tx group of 16 lanes)
        float mt[4];
#pragma unroll
        for (int i = 0; i < 4; ++i) {
            float m = fmaxf(fmaxf(s[i][0], s[i][1]), fmaxf(s[i][2], s[i][3]));
#pragma unroll
            for (int off = 8; off; off >>= 1)
                m = fmaxf(m, __shfl_xor_sync(0xffffffffu, m, off));
            mt[i] = m;
        }

        float al[4];
#pragma unroll
        for (int i = 0; i < 4; ++i) {
            float mn = fmaxf(mrow[i], mt[i]);
            al[i]    = __expf(mrow[i] - mn);
            mrow[i]  = mn;
        }

        // p = exp(s - m); row sums; write P column-major
#pragma unroll
        for (int i = 0; i < 4; ++i) {
            float sum = 0.f;
#pragma unroll
            for (int j = 0; j < 4; ++j) {
                float p = __expf(s[i][j] - mrow[i]);
                s[i][j] = p;
                sum += p;
            }
#pragma unroll
            for (int off = 8; off; off >>= 1)
                sum += __shfl_xor_sync(0xffffffffu, sum, off);
            lrow[i] = lrow[i] * al[i] + sum;
#pragma unroll
            for (int j = 0; j < 8; ++j) o[i][j] *= al[i];
        }
#pragma unroll
        for (int j = 0; j < 4; ++j) {
            float4 w = make_float4(s[0][j], s[1][j], s[2][j], s[3][j]);
            *reinterpret_cast<float4*>(Ps + (c0 + j) * 68 + r0) = w;
        }
        __syncthreads();

        // O += P V   (4 rows x 8 cols per thread)
#pragma unroll 2
        for (int kk = 0; kk < BN; ++kk) {
            float4 pw = *reinterpret_cast<const float4*>(Ps + kk * 68 + r0);
            float p4[4] = {pw.x, pw.y, pw.z, pw.w};
            float4 v0 = *reinterpret_cast<const float4*>(Vs + kk * 132 + cc0);
            float4 v1 = *reinterpret_cast<const float4*>(Vs + kk * 132 + cc0 + 4);
            float vv[8] = {v0.x, v0.y, v0.z, v0.w, v1.x, v1.y, v1.z, v1.w};
#pragma unroll
            for (int i = 0; i < 4; ++i)
#pragma unroll
                for (int j = 0; j < 8; ++j)
                    o[i][j] = fmaf(p4[i], vv[j], o[i][j]);
        }
        __syncthreads();
    }

    // epilogue: normalize and write to g_attn [B*S, H*DK]
    size_t qrow_base = (size_t)b * SEQ + (size_t)qt * BM;
#pragma unroll
    for (int i = 0; i < 4; ++i) {
        float inv = 1.f / lrow[i];
        size_t base = (qrow_base + r0 + i) * DMODEL + (size_t)h * DHEAD + cc0;
        float4 w0 = make_float4(o[i][0] * inv, o[i][1] * inv, o[i][2] * inv, o[i][3] * inv);
        float4 w1 = make_float4(o[i][4] * inv, o[i][5] * inv, o[i][6] * inv, o[i][7] * inv);
        *reinterpret_cast<float4*>(O + base)     = w0;
        *reinterpret_cast<float4*>(O + base + 4) = w1;
    }
}

// ---------------- launch ------------------------------------------------------
extern "C" void kernel_launch(void* const* d_in, const int* in_sizes, int n_in,
                              void* d_out, int out_size)
{
    const float* x    = (const float*)d_in[0];
    const float* fcos = (const float*)d_in[1];
    const float* fsin = (const float*)d_in[2];
    const float* wq_w = (const float*)d_in[3];
    const float* wq_b = (const float*)d_in[4];
    const float* wk_w = (const float*)d_in[5];
    const float* wk_b = (const float*)d_in[6];
    const float* wv_w = (const float*)d_in[7];
    const float* wv_b = (const float*)d_in[8];
    const float* wo_w = (const float*)d_in[9];
    const float* wo_b = (const float*)d_in[10];
    float* out = (float*)d_out;

    static float *q = nullptr, *k, *v, *qh, *kh, *vh, *attn;
    static bool init_done = false;
    if (!init_done) {
        cudaGetSymbolAddress((void**)&q,    g_q);
        cudaGetSymbolAddress((void**)&k,    g_k);
        cudaGetSymbolAddress((void**)&v,    g_v);
        cudaGetSymbolAddress((void**)&qh,   g_qh);
        cudaGetSymbolAddress((void**)&kh,   g_kh);
        cudaGetSymbolAddress((void**)&vh,   g_vh);
        cudaGetSymbolAddress((void**)&attn, g_attn);
        cudaFuncSetAttribute(attn_kernel, cudaFuncAttributeMaxDynamicSharedMemorySize,
                             ATTN_SMEM_BYTES);
        init_done = true;
    }

    dim3 blk(256);

    // QKV projections
    gemm_nt_bias<<<dim3(DMODEL / 128, ROWS / 128), blk>>>(x, wq_w, wq_b, q, ROWS, DMODEL, DMODEL);
    gemm_nt_bias<<<dim3(KVD    / 128, ROWS / 128), blk>>>(x, wk_w, wk_b, k, ROWS, KVD,    DMODEL);
    gemm_nt_bias<<<dim3(KVD    / 128, ROWS / 128), blk>>>(x, wv_w, wv_b, v, ROWS, KVD,    DMODEL);

    // RoPE + head rearrangement
    {
        size_t totq = (size_t)ROWS * NH  * (DHEAD / 2);
        size_t totk = (size_t)ROWS * NKV * (DHEAD / 2);
        size_t totv = (size_t)ROWS * KVD;
        rope_heads<<<(unsigned)((totq + 255) / 256), 256>>>(q, qh, fcos, fsin, NH);
        rope_heads<<<(unsigned)((totk + 255) / 256), 256>>>(k, kh, fcos, fsin, NKV);
        v_heads  <<<(unsigned)((totv + 255) / 256), 256>>>(v, vh);
    }

    // causal GQA attention
    attn_kernel<<<dim3(SEQ / BM, NH, BATCH), blk, ATTN_SMEM_BYTES>>>(qh, kh, vh, attn);

    // output projection -> d_out
    gemm_nt_bias<<<dim3(DMODEL / 128, ROWS / 128), blk>>>(attn, wo_w, wo_b, out, ROWS, DMODEL, DMODEL);
}

// round 9
// speedup vs baseline: 1.5543x; 1.5514x over previous
#include <cuda_runtime.h>
#include <math.h>
#include <stdint.h>

#define BATCH  2
#define SEQ    2048
#define DMODEL 2048
#define NH     16
#define NKV    4
#define DHEAD  128
#define REP    (NH / NKV)
#define ROWS   (BATCH * SEQ)     /* 4096 */
#define KVD    (NKV * DHEAD)     /* 512  */

#define BM 64
#define BN 64

// ---------------- scratch (static device arrays; no allocation) --------------
__device__ float g_q[(size_t)ROWS * DMODEL];
__device__ float g_k[(size_t)ROWS * KVD];
__device__ float g_v[(size_t)ROWS * KVD];
__device__ float g_qh[(size_t)ROWS * DMODEL];
__device__ float g_kh[(size_t)ROWS * KVD];
__device__ float g_vh[(size_t)ROWS * KVD];
__device__ float g_attn[(size_t)ROWS * DMODEL];

// ============================================================================
// TF32 mma.sync GEMM:  C[M,N] = A[M,K] @ W[N,K]^T + bias
// CTA 128x128, BK=16, 256 threads (8 warps, 4x2), warp tile 32x64.
// m16n8k8 tf32 MMA; smem rows padded to 20 words (conflict-free fragments).
// ============================================================================

__device__ __forceinline__ uint32_t f2tf32(float x)
{
    uint32_t u;
    asm("cvt.rna.tf32.f32 %0, %1;" : "=r"(u) : "f"(x));
    return u;
}

__device__ __forceinline__ void mma_tf32(float* c, const uint32_t* a, const uint32_t* b)
{
    asm volatile(
        "mma.sync.aligned.m16n8k8.row.col.f32.tf32.tf32.f32 "
        "{%0,%1,%2,%3}, {%4,%5,%6,%7}, {%8,%9}, {%0,%1,%2,%3};"
        : "+f"(c[0]), "+f"(c[1]), "+f"(c[2]), "+f"(c[3])
        : "r"(a[0]), "r"(a[1]), "r"(a[2]), "r"(a[3]),
          "r"(b[0]), "r"(b[1]));
}

#define LDW 20   /* smem row stride in words: 16 data + 4 pad */

__global__ __launch_bounds__(256) void gemm_mma_tf32(
    const float* __restrict__ A, const float* __restrict__ W,
    const float* __restrict__ bias, float* __restrict__ C,
    int M, int N, int K)
{
    __shared__ float As[128][LDW];
    __shared__ float Ws[128][LDW];

    const int tid  = threadIdx.x;
    const int wid  = tid >> 5;
    const int lane = tid & 31;
    const int grp  = lane >> 2;   // 0..7
    const int q    = lane & 3;    // 0..3
    const int wm   = wid & 3;     // warp row   (4 in M)
    const int wn   = wid >> 2;    // warp col   (2 in N)
    const int m0   = blockIdx.y << 7;
    const int n0   = blockIdx.x << 7;

    const int lrow = tid >> 2;          // 0..63 (fill row)
    const int lcol = (tid & 3) << 2;    // 0,4,8,12 (fill col)

    float acc[2][8][4];
#pragma unroll
    for (int mt = 0; mt < 2; ++mt)
#pragma unroll
        for (int nt = 0; nt < 8; ++nt)
#pragma unroll
            for (int j = 0; j < 4; ++j) acc[mt][nt][j] = 0.f;

    const float* Arow0 = A + (size_t)(m0 + lrow) * K + lcol;
    const float* Arow1 = A + (size_t)(m0 + lrow + 64) * K + lcol;
    const float* Wrow0 = W + (size_t)(n0 + lrow) * K + lcol;
    const float* Wrow1 = W + (size_t)(n0 + lrow + 64) * K + lcol;

    const int niter = K >> 4;

    float4 ra0 = *reinterpret_cast<const float4*>(Arow0);
    float4 ra1 = *reinterpret_cast<const float4*>(Arow1);
    float4 rw0 = *reinterpret_cast<const float4*>(Wrow0);
    float4 rw1 = *reinterpret_cast<const float4*>(Wrow1);

    for (int it = 0; it < niter; ++it) {
        // store (with TF32 RNA rounding folded in)
        {
            uint32_t* d;
            d = reinterpret_cast<uint32_t*>(&As[lrow][lcol]);
            d[0] = f2tf32(ra0.x); d[1] = f2tf32(ra0.y); d[2] = f2tf32(ra0.z); d[3] = f2tf32(ra0.w);
            d = reinterpret_cast<uint32_t*>(&As[lrow + 64][lcol]);
            d[0] = f2tf32(ra1.x); d[1] = f2tf32(ra1.y); d[2] = f2tf32(ra1.z); d[3] = f2tf32(ra1.w);
            d = reinterpret_cast<uint32_t*>(&Ws[lrow][lcol]);
            d[0] = f2tf32(rw0.x); d[1] = f2tf32(rw0.y); d[2] = f2tf32(rw0.z); d[3] = f2tf32(rw0.w);
            d = reinterpret_cast<uint32_t*>(&Ws[lrow + 64][lcol]);
            d[0] = f2tf32(rw1.x); d[1] = f2tf32(rw1.y); d[2] = f2tf32(rw1.z); d[3] = f2tf32(rw1.w);
        }
        __syncthreads();

        // prefetch next tile (LDG overlaps compute below)
        if (it + 1 < niter) {
            int ko = (it + 1) << 4;
            ra0 = *reinterpret_cast<const float4*>(Arow0 + ko);
            ra1 = *reinterpret_cast<const float4*>(Arow1 + ko);
            rw0 = *reinterpret_cast<const float4*>(Wrow0 + ko);
            rw1 = *reinterpret_cast<const float4*>(Wrow1 + ko);
        }

        // compute: 2 k-steps of m16n8k8
#pragma unroll
        for (int kk = 0; kk < 2; ++kk) {
            const int kb = kk << 3;
            uint32_t af[2][4];
#pragma unroll
            for (int mt = 0; mt < 2; ++mt) {
                const uint32_t* base = reinterpret_cast<const uint32_t*>(
                    &As[wm * 32 + mt * 16 + grp][kb + q]);
                af[mt][0] = base[0];
                af[mt][1] = base[8 * LDW];
                af[mt][2] = base[4];
                af[mt][3] = base[8 * LDW + 4];
            }
            uint32_t bf[8][2];
#pragma unroll
            for (int nt = 0; nt < 8; ++nt) {
                const uint32_t* base = reinterpret_cast<const uint32_t*>(
                    &Ws[wn * 64 + nt * 8 + grp][kb + q]);
                bf[nt][0] = base[0];
                bf[nt][1] = base[4];
            }
#pragma unroll
            for (int mt = 0; mt < 2; ++mt)
#pragma unroll
                for (int nt = 0; nt < 8; ++nt)
                    mma_tf32(acc[mt][nt], af[mt], bf[nt]);
        }
        __syncthreads();
    }

    // epilogue
#pragma unroll
    for (int mt = 0; mt < 2; ++mt) {
        const int m = m0 + wm * 32 + mt * 16 + grp;
#pragma unroll
        for (int nt = 0; nt < 8; ++nt) {
            const int n = n0 + wn * 64 + nt * 8 + 2 * q;
            float2 b2 = *reinterpret_cast<const float2*>(bias + n);
            float2 o0, o1;
            o0.x = acc[mt][nt][0] + b2.x;
            o0.y = acc[mt][nt][1] + b2.y;
            o1.x = acc[mt][nt][2] + b2.x;
            o1.y = acc[mt][nt][3] + b2.y;
            *reinterpret_cast<float2*>(C + (size_t)m * N + n)       = o0;
            *reinterpret_cast<float2*>(C + (size_t)(m + 8) * N + n) = o1;
        }
    }
}

// ---------------- RoPE + [B*S, H*DK] -> [B,H,S,DK] ---------------------------
__global__ void rope_heads(const float* __restrict__ src, float* __restrict__ dst,
                           const float* __restrict__ cosp, const float* __restrict__ sinp,
                           int nheads)
{
    size_t idx = (size_t)blockIdx.x * blockDim.x + threadIdx.x;   // pair index
    size_t total = (size_t)ROWS * nheads * (DHEAD / 2);
    if (idx >= total) return;
    int i = (int)(idx & 63);
    int h = (int)((idx >> 6) % nheads);
    size_t row = idx / ((size_t)nheads * 64);
    int s = (int)(row & (SEQ - 1));
    int b = (int)(row >> 11);

    float2 t = *reinterpret_cast<const float2*>(src + (row * nheads + h) * DHEAD + 2 * i);
    float c  = cosp[s * 64 + i];
    float sn = sinp[s * 64 + i];
    float2 o;
    o.x = t.x * c - t.y * sn;
    o.y = t.x * sn + t.y * c;
    *reinterpret_cast<float2*>(dst + ((size_t)(b * nheads + h) * SEQ + s) * DHEAD + 2 * i) = o;
}

// ---------------- V: [B*S, HK*DK] -> [B,HK,S,DK] ------------------------------
__global__ void v_heads(const float* __restrict__ src, float* __restrict__ dst)
{
    size_t idx = (size_t)blockIdx.x * blockDim.x + threadIdx.x;
    if (idx >= (size_t)ROWS * KVD) return;
    int d = (int)(idx & 127);
    int h = (int)((idx >> 7) & 3);
    size_t row = idx >> 9;
    int s = (int)(row & (SEQ - 1));
    int b = (int)(row >> 11);
    dst[((size_t)(b * NKV + h) * SEQ + s) * DHEAD + d] = src[idx];
}

// ---------------- Flash attention (fp32, causal, GQA) -------------------------
#define ATTN_SMEM_WORDS (128 * 68 + 128 * 68 + 64 * 132 + 64 * 68)
#define ATTN_SMEM_BYTES (ATTN_SMEM_WORDS * 4)

__global__ __launch_bounds__(256) void attn_kernel(
    const float* __restrict__ Q, const float* __restrict__ K,
    const float* __restrict__ V, float* __restrict__ O)
{
    extern __shared__ float sm[];
    float* Qs = sm;                  // [128][68]
    float* Ks = Qs + 128 * 68;       // [128][68]
    float* Vs = Ks + 128 * 68;       // [64][132]
    float* Ps = Vs + 64 * 132;       // [64][68] column-major

    const int tid = threadIdx.x;
    const int tx  = tid & 15;
    const int ty  = tid >> 4;
    const int qt  = blockIdx.x;
    const int h   = blockIdx.y;
    const int b   = blockIdx.z;
    const int g   = h / REP;

    const float* Qp = Q + ((size_t)(b * NH  + h) * SEQ + (size_t)qt * BM) * DHEAD;
    const float* Kp = K + ((size_t)(b * NKV + g) * SEQ) * DHEAD;
    const float* Vp = V + ((size_t)(b * NKV + g) * SEQ) * DHEAD;

    const float scale = 0.08838834764831845f;  // 1/sqrt(128)

    for (int idx = tid; idx < BM * DHEAD; idx += 256) {
        int r = idx >> 7;
        int d = idx & 127;
        Qs[d * 68 + r] = Qp[idx] * scale;
    }

    const int r0  = ty * 4;
    const int c0  = tx * 4;
    const int cc0 = tx * 8;

    float o[4][8];
#pragma unroll
    for (int i = 0; i < 4; ++i)
#pragma unroll
        for (int j = 0; j < 8; ++j) o[i][j] = 0.f;
    float mrow[4] = {-INFINITY, -INFINITY, -INFINITY, -INFINITY};
    float lrow[4] = {0.f, 0.f, 0.f, 0.f};

    for (int kt = 0; kt <= qt; ++kt) {
        for (int idx = tid; idx < BN * DHEAD; idx += 256) {
            int c = idx >> 7;
            int d = idx & 127;
            size_t goff = (size_t)kt * BN * DHEAD + idx;
            Ks[d * 68 + c]  = Kp[goff];
            Vs[c * 132 + d] = Vp[goff];
        }
        __syncthreads();

        float s[4][4];
#pragma unroll
        for (int i = 0; i < 4; ++i)
#pragma unroll
            for (int j = 0; j < 4; ++j) s[i][j] = 0.f;

#pragma unroll 4
        for (int d = 0; d < DHEAD; ++d) {
            float a[4], bb[4];
            *reinterpret_cast<float4*>(a)  = *reinterpret_cast<const float4*>(Qs + d * 68 + r0);
            *reinterpret_cast<float4*>(bb) = *reinterpret_cast<const float4*>(Ks + d * 68 + c0);
#pragma unroll
            for (int i = 0; i < 4; ++i)
#pragma unroll
                for (int j = 0; j < 4; ++j)
                    s[i][j] = fmaf(a[i], bb[j], s[i][j]);
        }

        if (kt == qt) {
#pragma unroll
            for (int i = 0; i < 4; ++i)
#pragma unroll
                for (int j = 0; j < 4; ++j)
                    if (c0 + j > r0 + i) s[i][j] = -INFINITY;
        }

        float mt[4];
#pragma unroll
        for (int i = 0; i < 4; ++i) {
            float m = fmaxf(fmaxf(s[i][0], s[i][1]), fmaxf(s[i][2], s[i][3]));
#pragma unroll
            for (int off = 8; off; off >>= 1)
                m = fmaxf(m, __shfl_xor_sync(0xffffffffu, m, off));
            mt[i] = m;
        }

        float al[4];
#pragma unroll
        for (int i = 0; i < 4; ++i) {
            float mn = fmaxf(mrow[i], mt[i]);
            al[i]    = __expf(mrow[i] - mn);
            mrow[i]  = mn;
        }

#pragma unroll
        for (int i = 0; i < 4; ++i) {
            float sum = 0.f;
#pragma unroll
            for (int j = 0; j < 4; ++j) {
                float p = __expf(s[i][j] - mrow[i]);
                s[i][j] = p;
                sum += p;
            }
#pragma unroll
            for (int off = 8; off; off >>= 1)
                sum += __shfl_xor_sync(0xffffffffu, sum, off);
            lrow[i] = lrow[i] * al[i] + sum;
#pragma unroll
            for (int j = 0; j < 8; ++j) o[i][j] *= al[i];
        }
#pragma unroll
        for (int j = 0; j < 4; ++j) {
            float4 w = make_float4(s[0][j], s[1][j], s[2][j], s[3][j]);
            *reinterpret_cast<float4*>(Ps + (c0 + j) * 68 + r0) = w;
        }
        __syncthreads();

#pragma unroll 2
        for (int kk = 0; kk < BN; ++kk) {
            float4 pw = *reinterpret_cast<const float4*>(Ps + kk * 68 + r0);
            float p4[4] = {pw.x, pw.y, pw.z, pw.w};
            float4 v0 = *reinterpret_cast<const float4*>(Vs + kk * 132 + cc0);
            float4 v1 = *reinterpret_cast<const float4*>(Vs + kk * 132 + cc0 + 4);
            float vv[8] = {v0.x, v0.y, v0.z, v0.w, v1.x, v1.y, v1.z, v1.w};
#pragma unroll
            for (int i = 0; i < 4; ++i)
#pragma unroll
                for (int j = 0; j < 8; ++j)
                    o[i][j] = fmaf(p4[i], vv[j], o[i][j]);
        }
        __syncthreads();
    }

    size_t qrow_base = (size_t)b * SEQ + (size_t)qt * BM;
#pragma unroll
    for (int i = 0; i < 4; ++i) {
        float inv = 1.f / lrow[i];
        size_t base = (qrow_base + r0 + i) * DMODEL + (size_t)h * DHEAD + cc0;
        float4 w0 = make_float4(o[i][0] * inv, o[i][1] * inv, o[i][2] * inv, o[i][3] * inv);
        float4 w1 = make_float4(o[i][4] * inv, o[i][5] * inv, o[i][6] * inv, o[i][7] * inv);
        *reinterpret_cast<float4*>(O + base)     = w0;
        *reinterpret_cast<float4*>(O + base + 4) = w1;
    }
}

// ---------------- launch ------------------------------------------------------
extern "C" void kernel_launch(void* const* d_in, const int* in_sizes, int n_in,
                              void* d_out, int out_size)
{
    const float* x    = (const float*)d_in[0];
    const float* fcos = (const float*)d_in[1];
    const float* fsin = (const float*)d_in[2];
    const float* wq_w = (const float*)d_in[3];
    const float* wq_b = (const float*)d_in[4];
    const float* wk_w = (const float*)d_in[5];
    const float* wk_b = (const float*)d_in[6];
    const float* wv_w = (const float*)d_in[7];
    const float* wv_b = (const float*)d_in[8];
    const float* wo_w = (const float*)d_in[9];
    const float* wo_b = (const float*)d_in[10];
    float* out = (float*)d_out;

    static float *q = nullptr, *k, *v, *qh, *kh, *vh, *attn;
    static bool init_done = false;
    if (!init_done) {
        cudaGetSymbolAddress((void**)&q,    g_q);
        cudaGetSymbolAddress((void**)&k,    g_k);
        cudaGetSymbolAddress((void**)&v,    g_v);
        cudaGetSymbolAddress((void**)&qh,   g_qh);
        cudaGetSymbolAddress((void**)&kh,   g_kh);
        cudaGetSymbolAddress((void**)&vh,   g_vh);
        cudaGetSymbolAddress((void**)&attn, g_attn);
        cudaFuncSetAttribute(attn_kernel, cudaFuncAttributeMaxDynamicSharedMemorySize,
                             ATTN_SMEM_BYTES);
        init_done = true;
    }

    // QKV projections (TF32 mma.sync tensor cores)
    gemm_mma_tf32<<<dim3(DMODEL / 128, ROWS / 128), 256>>>(x, wq_w, wq_b, q, ROWS, DMODEL, DMODEL);
    gemm_mma_tf32<<<dim3(KVD    / 128, ROWS / 128), 256>>>(x, wk_w, wk_b, k, ROWS, KVD,    DMODEL);
    gemm_mma_tf32<<<dim3(KVD    / 128, ROWS / 128), 256>>>(x, wv_w, wv_b, v, ROWS, KVD,    DMODEL);

    // RoPE + head rearrangement
    {
        size_t totq = (size_t)ROWS * NH  * (DHEAD / 2);
        size_t totk = (size_t)ROWS * NKV * (DHEAD / 2);
        size_t totv = (size_t)ROWS * KVD;
        rope_heads<<<(unsigned)((totq + 255) / 256), 256>>>(q, qh, fcos, fsin, NH);
        rope_heads<<<(unsigned)((totk + 255) / 256), 256>>>(k, kh, fcos, fsin, NKV);
        v_heads  <<<(unsigned)((totv + 255) / 256), 256>>>(v, vh);
    }

    // causal GQA attention (fp32 SIMT — next optimization target)
    attn_kernel<<<dim3(SEQ / BM, NH, BATCH), 256, ATTN_SMEM_BYTES>>>(qh, kh, vh, attn);

    // output projection -> d_out (TF32 mma.sync)
    gemm_mma_tf32<<<dim3(DMODEL / 128, ROWS / 128), 256>>>(attn, wo_w, wo_b, out, ROWS, DMODEL, DMODEL);
}

// round 10
// speedup vs baseline: 2.8007x; 1.8020x over previous
#include <cuda_runtime.h>
#include <math.h>
#include <stdint.h>

#define BATCH  2
#define SEQ    2048
#define DMODEL 2048
#define NH     16
#define NKV    4
#define DHEAD  128
#define REP    (NH / NKV)
#define ROWS   (BATCH * SEQ)     /* 4096 */
#define KVD    (NKV * DHEAD)     /* 512  */

// ---------------- scratch (static device arrays; no allocation) --------------
__device__ float g_q[(size_t)ROWS * DMODEL];
__device__ float g_k[(size_t)ROWS * KVD];
__device__ float g_v[(size_t)ROWS * KVD];
__device__ float g_qh[(size_t)ROWS * DMODEL];
__device__ float g_kh[(size_t)ROWS * KVD];
__device__ float g_vh[(size_t)ROWS * KVD];
__device__ float g_attn[(size_t)ROWS * DMODEL];

__device__ __forceinline__ uint32_t f2tf32(float x)
{
    uint32_t u;
    asm("cvt.rna.tf32.f32 %0, %1;" : "=r"(u) : "f"(x));
    return u;
}

__device__ __forceinline__ void mma_tf32(float* c, const uint32_t* a, const uint32_t* b)
{
    asm volatile(
        "mma.sync.aligned.m16n8k8.row.col.f32.tf32.tf32.f32 "
        "{%0,%1,%2,%3}, {%4,%5,%6,%7}, {%8,%9}, {%0,%1,%2,%3};"
        : "+f"(c[0]), "+f"(c[1]), "+f"(c[2]), "+f"(c[3])
        : "r"(a[0]), "r"(a[1]), "r"(a[2]), "r"(a[3]),
          "r"(b[0]), "r"(b[1]));
}

// ============================================================================
// TF32 mma.sync GEMM (double-buffered smem):  C = A @ W^T + bias
// CTA 128x128, BK=16, 256 threads (8 warps, 4x2), warp tile 32x64.
// ============================================================================
#define LDW 20   /* smem row stride in words: 16 data + 4 pad */

__global__ __launch_bounds__(256) void gemm_mma_tf32(
    const float* __restrict__ A, const float* __restrict__ W,
    const float* __restrict__ bias, float* __restrict__ C,
    int M, int N, int K)
{
    __shared__ float As[2][128][LDW];
    __shared__ float Ws[2][128][LDW];

    const int tid  = threadIdx.x;
    const int wid  = tid >> 5;
    const int lane = tid & 31;
    const int grp  = lane >> 2;   // 0..7
    const int q    = lane & 3;    // 0..3
    const int wm   = wid & 3;     // warp row   (4 in M)
    const int wn   = wid >> 2;    // warp col   (2 in N)
    const int m0   = blockIdx.y << 7;
    const int n0   = blockIdx.x << 7;

    const int lrow = tid >> 2;          // 0..63 (fill row)
    const int lcol = (tid & 3) << 2;    // 0,4,8,12 (fill col)

    float acc[2][8][4];
#pragma unroll
    for (int mt = 0; mt < 2; ++mt)
#pragma unroll
        for (int nt = 0; nt < 8; ++nt)
#pragma unroll
            for (int j = 0; j < 4; ++j) acc[mt][nt][j] = 0.f;

    const float* Arow0 = A + (size_t)(m0 + lrow) * K + lcol;
    const float* Arow1 = A + (size_t)(m0 + lrow + 64) * K + lcol;
    const float* Wrow0 = W + (size_t)(n0 + lrow) * K + lcol;
    const float* Wrow1 = W + (size_t)(n0 + lrow + 64) * K + lcol;

    const int niter = K >> 4;

    float4 ra0 = *reinterpret_cast<const float4*>(Arow0);
    float4 ra1 = *reinterpret_cast<const float4*>(Arow1);
    float4 rw0 = *reinterpret_cast<const float4*>(Wrow0);
    float4 rw1 = *reinterpret_cast<const float4*>(Wrow1);

    // fill buffer 0
    {
        uint32_t* d;
        d = reinterpret_cast<uint32_t*>(&As[0][lrow][lcol]);
        d[0] = f2tf32(ra0.x); d[1] = f2tf32(ra0.y); d[2] = f2tf32(ra0.z); d[3] = f2tf32(ra0.w);
        d = reinterpret_cast<uint32_t*>(&As[0][lrow + 64][lcol]);
        d[0] = f2tf32(ra1.x); d[1] = f2tf32(ra1.y); d[2] = f2tf32(ra1.z); d[3] = f2tf32(ra1.w);
        d = reinterpret_cast<uint32_t*>(&Ws[0][lrow][lcol]);
        d[0] = f2tf32(rw0.x); d[1] = f2tf32(rw0.y); d[2] = f2tf32(rw0.z); d[3] = f2tf32(rw0.w);
        d = reinterpret_cast<uint32_t*>(&Ws[0][lrow + 64][lcol]);
        d[0] = f2tf32(rw1.x); d[1] = f2tf32(rw1.y); d[2] = f2tf32(rw1.z); d[3] = f2tf32(rw1.w);
    }
    __syncthreads();

    for (int it = 0; it < niter; ++it) {
        const int cur = it & 1;
        // prefetch next tile (gmem)
        if (it + 1 < niter) {
            int ko = (it + 1) << 4;
            ra0 = *reinterpret_cast<const float4*>(Arow0 + ko);
            ra1 = *reinterpret_cast<const float4*>(Arow1 + ko);
            rw0 = *reinterpret_cast<const float4*>(Wrow0 + ko);
            rw1 = *reinterpret_cast<const float4*>(Wrow1 + ko);
        }

        // compute on current buffer
#pragma unroll
        for (int kk = 0; kk < 2; ++kk) {
            const int kb = kk << 3;
            uint32_t af[2][4];
#pragma unroll
            for (int mt = 0; mt < 2; ++mt) {
                const uint32_t* base = reinterpret_cast<const uint32_t*>(
                    &As[cur][wm * 32 + mt * 16 + grp][kb + q]);
                af[mt][0] = base[0];
                af[mt][1] = base[8 * LDW];
                af[mt][2] = base[4];
                af[mt][3] = base[8 * LDW + 4];
            }
            uint32_t bf[8][2];
#pragma unroll
            for (int nt = 0; nt < 8; ++nt) {
                const uint32_t* base = reinterpret_cast<const uint32_t*>(
                    &Ws[cur][wn * 64 + nt * 8 + grp][kb + q]);
                bf[nt][0] = base[0];
                bf[nt][1] = base[4];
            }
#pragma unroll
            for (int mt = 0; mt < 2; ++mt)
#pragma unroll
                for (int nt = 0; nt < 8; ++nt)
                    mma_tf32(acc[mt][nt], af[mt], bf[nt]);
        }

        // store next tile into other buffer (overlaps with other warps' compute)
        if (it + 1 < niter) {
            const int nxt = cur ^ 1;
            uint32_t* d;
            d = reinterpret_cast<uint32_t*>(&As[nxt][lrow][lcol]);
            d[0] = f2tf32(ra0.x); d[1] = f2tf32(ra0.y); d[2] = f2tf32(ra0.z); d[3] = f2tf32(ra0.w);
            d = reinterpret_cast<uint32_t*>(&As[nxt][lrow + 64][lcol]);
            d[0] = f2tf32(ra1.x); d[1] = f2tf32(ra1.y); d[2] = f2tf32(ra1.z); d[3] = f2tf32(ra1.w);
            d = reinterpret_cast<uint32_t*>(&Ws[nxt][lrow][lcol]);
            d[0] = f2tf32(rw0.x); d[1] = f2tf32(rw0.y); d[2] = f2tf32(rw0.z); d[3] = f2tf32(rw0.w);
            d = reinterpret_cast<uint32_t*>(&Ws[nxt][lrow + 64][lcol]);
            d[0] = f2tf32(rw1.x); d[1] = f2tf32(rw1.y); d[2] = f2tf32(rw1.z); d[3] = f2tf32(rw1.w);
        }
        __syncthreads();
    }

    // epilogue
#pragma unroll
    for (int mt = 0; mt < 2; ++mt) {
        const int m = m0 + wm * 32 + mt * 16 + grp;
#pragma unroll
        for (int nt = 0; nt < 8; ++nt) {
            const int n = n0 + wn * 64 + nt * 8 + 2 * q;
            float2 b2 = *reinterpret_cast<const float2*>(bias + n);
            float2 o0, o1;
            o0.x = acc[mt][nt][0] + b2.x;
            o0.y = acc[mt][nt][1] + b2.y;
            o1.x = acc[mt][nt][2] + b2.x;
            o1.y = acc[mt][nt][3] + b2.y;
            *reinterpret_cast<float2*>(C + (size_t)m * N + n)       = o0;
            *reinterpret_cast<float2*>(C + (size_t)(m + 8) * N + n) = o1;
        }
    }
}

// ---------------- RoPE + [B*S, H*DK] -> [B,H,S,DK] ---------------------------
__global__ void rope_heads(const float* __restrict__ src, float* __restrict__ dst,
                           const float* __restrict__ cosp, const float* __restrict__ sinp,
                           int nheads)
{
    size_t idx = (size_t)blockIdx.x * blockDim.x + threadIdx.x;   // pair index
    size_t total = (size_t)ROWS * nheads * (DHEAD / 2);
    if (idx >= total) return;
    int i = (int)(idx & 63);
    int h = (int)((idx >> 6) % nheads);
    size_t row = idx / ((size_t)nheads * 64);
    int s = (int)(row & (SEQ - 1));
    int b = (int)(row >> 11);

    float2 t = *reinterpret_cast<const float2*>(src + (row * nheads + h) * DHEAD + 2 * i);
    float c  = cosp[s * 64 + i];
    float sn = sinp[s * 64 + i];
    float2 o;
    o.x = t.x * c - t.y * sn;
    o.y = t.x * sn + t.y * c;
    *reinterpret_cast<float2*>(dst + ((size_t)(b * nheads + h) * SEQ + s) * DHEAD + 2 * i) = o;
}

// ---------------- V: [B*S, HK*DK] -> [B,HK,S,DK] ------------------------------
__global__ void v_heads(const float* __restrict__ src, float* __restrict__ dst)
{
    size_t idx = (size_t)blockIdx.x * blockDim.x + threadIdx.x;
    if (idx >= (size_t)ROWS * KVD) return;
    int d = (int)(idx & 127);
    int h = (int)((idx >> 7) & 3);
    size_t row = idx >> 9;
    int s = (int)(row & (SEQ - 1));
    int b = (int)(row >> 11);
    dst[((size_t)(b * NKV + h) * SEQ + s) * DHEAD + d] = src[idx];
}

// ============================================================================
// Flash attention, TF32 mma.sync, causal, GQA.
// CTA: 256 threads (8 warps), BM=128 (warp = 16 rows), BN=64, DK=128.
// ============================================================================
#define AQ_LD 132
#define AK_LD 132
#define AV_LD 136
#define AP_LD 68
#define ATTN_SMEM_WORDS (128*AQ_LD + 64*AK_LD + 64*AV_LD + 128*AP_LD)
#define ATTN_SMEM_BYTES (ATTN_SMEM_WORDS * 4)

__global__ __launch_bounds__(256, 1) void attn_mma(
    const float* __restrict__ Q, const float* __restrict__ K,
    const float* __restrict__ V, float* __restrict__ O)
{
    extern __shared__ float sm[];
    float* Qs = sm;                        // [128][AQ_LD] tf32 bits, pre-scaled
    float* Ks = Qs + 128 * AQ_LD;          // [64][AK_LD]  tf32 bits
    float* Vs = Ks + 64 * AK_LD;           // [64][AV_LD]  tf32 bits
    float* Ps = Vs + 64 * AV_LD;           // [128][AP_LD] tf32 bits (per-warp rows)

    const int tid  = threadIdx.x;
    const int wid  = tid >> 5;
    const int lane = tid & 31;
    const int grp  = lane >> 2;   // 0..7
    const int qd   = lane & 3;    // 0..3
    const int qt   = blockIdx.x;
    const int h    = blockIdx.y;
    const int b    = blockIdx.z;
    const int g    = h / REP;
    const int mbase = wid * 16;

    const float* Qp = Q + ((size_t)(b * NH  + h) * SEQ + (size_t)qt * 128) * DHEAD;
    const float* Kp = K + ((size_t)(b * NKV + g) * SEQ) * DHEAD;
    const float* Vp = V + ((size_t)(b * NKV + g) * SEQ) * DHEAD;

    const float scale = 0.08838834764831845f;  // 1/sqrt(128)

    // Load Q tile (128x128), scale + tf32-round, row-major
    for (int idx = tid; idx < 128 * 32; idx += 256) {
        int row = idx >> 5;
        int c4  = (idx & 31) << 2;
        float4 v = *reinterpret_cast<const float4*>(Qp + (size_t)row * DHEAD + c4);
        uint32_t* d = reinterpret_cast<uint32_t*>(Qs + row * AQ_LD + c4);
        d[0] = f2tf32(v.x * scale); d[1] = f2tf32(v.y * scale);
        d[2] = f2tf32(v.z * scale); d[3] = f2tf32(v.w * scale);
    }

    float o[16][4];
#pragma unroll
    for (int nt = 0; nt < 16; ++nt)
#pragma unroll
        for (int j = 0; j < 4; ++j) o[nt][j] = 0.f;
    float m0r = -INFINITY, m1r = -INFINITY;
    float l0 = 0.f, l1 = 0.f;

    const int row0 = qt * 128 + mbase + grp;
    const int row1 = row0 + 8;
    const int nkt  = 2 * qt + 2;

    for (int kt = 0; kt < nkt; ++kt) {
        __syncthreads();   // previous iter's PV reads done before refill (also covers Q fill on kt=0)

        // fill K,V tiles (64x128 each), tf32-rounded
        for (int idx = tid; idx < 64 * 32; idx += 256) {
            int row = idx >> 5;
            int c4  = (idx & 31) << 2;
            size_t goff = ((size_t)kt * 64 + row) * DHEAD + c4;
            float4 kv = *reinterpret_cast<const float4*>(Kp + goff);
            float4 vv = *reinterpret_cast<const float4*>(Vp + goff);
            uint32_t* dk = reinterpret_cast<uint32_t*>(Ks + row * AK_LD + c4);
            dk[0] = f2tf32(kv.x); dk[1] = f2tf32(kv.y);
            dk[2] = f2tf32(kv.z); dk[3] = f2tf32(kv.w);
            uint32_t* dv = reinterpret_cast<uint32_t*>(Vs + row * AV_LD + c4);
            dv[0] = f2tf32(vv.x); dv[1] = f2tf32(vv.y);
            dv[2] = f2tf32(vv.z); dv[3] = f2tf32(vv.w);
        }
        __syncthreads();

        // ---- S = Q K^T : warp computes 16x64, 16 k-steps ----
        float sacc[8][4];
#pragma unroll
        for (int nt = 0; nt < 8; ++nt)
#pragma unroll
            for (int j = 0; j < 4; ++j) sacc[nt][j] = 0.f;

#pragma unroll
        for (int ks = 0; ks < 16; ++ks) {
            uint32_t a[4];
            const uint32_t* abase = reinterpret_cast<const uint32_t*>(
                Qs + (mbase + grp) * AQ_LD + ks * 8 + qd);
            a[0] = abase[0];
            a[1] = abase[8 * AQ_LD];
            a[2] = abase[4];
            a[3] = abase[8 * AQ_LD + 4];
#pragma unroll
            for (int nt = 0; nt < 8; ++nt) {
                uint32_t bb[2];
                const uint32_t* bbase = reinterpret_cast<const uint32_t*>(
                    Ks + (nt * 8 + grp) * AK_LD + ks * 8 + qd);
                bb[0] = bbase[0];
                bb[1] = bbase[4];
                mma_tf32(sacc[nt], a, bb);
            }
        }

        // ---- causal mask (partial tiles only) ----
        if (kt >= 2 * qt) {
            const int colb = kt * 64;
#pragma unroll
            for (int nt = 0; nt < 8; ++nt) {
                int c = colb + nt * 8 + 2 * qd;
                if (c     > row0) sacc[nt][0] = -INFINITY;
                if (c + 1 > row0) sacc[nt][1] = -INFINITY;
                if (c     > row1) sacc[nt][2] = -INFINITY;
                if (c + 1 > row1) sacc[nt][3] = -INFINITY;
            }
        }

        // ---- online softmax (rows row0, row1) ----
        float mt0 = -INFINITY, mt1 = -INFINITY;
#pragma unroll
        for (int nt = 0; nt < 8; ++nt) {
            mt0 = fmaxf(mt0, fmaxf(sacc[nt][0], sacc[nt][1]));
            mt1 = fmaxf(mt1, fmaxf(sacc[nt][2], sacc[nt][3]));
        }
        mt0 = fmaxf(mt0, __shfl_xor_sync(0xffffffffu, mt0, 1));
        mt0 = fmaxf(mt0, __shfl_xor_sync(0xffffffffu, mt0, 2));
        mt1 = fmaxf(mt1, __shfl_xor_sync(0xffffffffu, mt1, 1));
        mt1 = fmaxf(mt1, __shfl_xor_sync(0xffffffffu, mt1, 2));

        float mn0 = fmaxf(m0r, mt0), mn1 = fmaxf(m1r, mt1);
        float al0 = __expf(m0r - mn0), al1 = __expf(m1r - mn1);
        m0r = mn0; m1r = mn1;

        float sum0 = 0.f, sum1 = 0.f;
#pragma unroll
        for (int nt = 0; nt < 8; ++nt) {
            float p0 = __expf(sacc[nt][0] - m0r);
            float p1 = __expf(sacc[nt][1] - m0r);
            float p2 = __expf(sacc[nt][2] - m1r);
            float p3 = __expf(sacc[nt][3] - m1r);
            sum0 += p0 + p1;
            sum1 += p2 + p3;
            uint32_t* d0 = reinterpret_cast<uint32_t*>(
                Ps + (mbase + grp) * AP_LD + nt * 8 + 2 * qd);
            d0[0] = f2tf32(p0); d0[1] = f2tf32(p1);
            uint32_t* d1 = reinterpret_cast<uint32_t*>(
                Ps + (mbase + grp + 8) * AP_LD + nt * 8 + 2 * qd);
            d1[0] = f2tf32(p2); d1[1] = f2tf32(p3);
        }
        sum0 += __shfl_xor_sync(0xffffffffu, sum0, 1);
        sum0 += __shfl_xor_sync(0xffffffffu, sum0, 2);
        sum1 += __shfl_xor_sync(0xffffffffu, sum1, 1);
        sum1 += __shfl_xor_sync(0xffffffffu, sum1, 2);
        l0 = l0 * al0 + sum0;
        l1 = l1 * al1 + sum1;

        // rescale O
#pragma unroll
        for (int nt = 0; nt < 16; ++nt) {
            o[nt][0] *= al0; o[nt][1] *= al0;
            o[nt][2] *= al1; o[nt][3] *= al1;
        }

        __syncwarp();   // Ps rows are warp-private; order STS -> LDS within warp

        // ---- O += P V : warp 16x128, 8 k-steps ----
#pragma unroll
        for (int ks = 0; ks < 8; ++ks) {
            uint32_t a[4];
            const uint32_t* abase = reinterpret_cast<const uint32_t*>(
                Ps + (mbase + grp) * AP_LD + ks * 8 + qd);
            a[0] = abase[0];
            a[1] = abase[8 * AP_LD];
            a[2] = abase[4];
            a[3] = abase[8 * AP_LD + 4];
#pragma unroll
            for (int nt = 0; nt < 16; ++nt) {
                uint32_t bb[2];
                const uint32_t* bbase = reinterpret_cast<const uint32_t*>(
                    Vs + (ks * 8 + qd) * AV_LD + nt * 8 + grp);
                bb[0] = bbase[0];
                bb[1] = bbase[4 * AV_LD];
                mma_tf32(o[nt], a, bb);
            }
        }
    }

    // ---- epilogue: normalize, write [B*S, D] at head column block ----
    float inv0 = 1.f / l0, inv1 = 1.f / l1;
    size_t gr0 = ((size_t)b * SEQ + qt * 128 + mbase + grp) * DMODEL + (size_t)h * DHEAD;
    size_t gr1 = gr0 + 8 * DMODEL;
#pragma unroll
    for (int nt = 0; nt < 16; ++nt) {
        int c = nt * 8 + 2 * qd;
        float2 w0, w1;
        w0.x = o[nt][0] * inv0; w0.y = o[nt][1] * inv0;
        w1.x = o[nt][2] * inv1; w1.y = o[nt][3] * inv1;
        *reinterpret_cast<float2*>(O + gr0 + c) = w0;
        *reinterpret_cast<float2*>(O + gr1 + c) = w1;
    }
}

// ---------------- launch ------------------------------------------------------
extern "C" void kernel_launch(void* const* d_in, const int* in_sizes, int n_in,
                              void* d_out, int out_size)
{
    const float* x    = (const float*)d_in[0];
    const float* fcos = (const float*)d_in[1];
    const float* fsin = (const float*)d_in[2];
    const float* wq_w = (const float*)d_in[3];
    const float* wq_b = (const float*)d_in[4];
    const float* wk_w = (const float*)d_in[5];
    const float* wk_b = (const float*)d_in[6];
    const float* wv_w = (const float*)d_in[7];
    const float* wv_b = (const float*)d_in[8];
    const float* wo_w = (const float*)d_in[9];
    const float* wo_b = (const float*)d_in[10];
    float* out = (float*)d_out;

    static float *q = nullptr, *k, *v, *qh, *kh, *vh, *attn;
    static bool init_done = false;
    if (!init_done) {
        cudaGetSymbolAddress((void**)&q,    g_q);
        cudaGetSymbolAddress((void**)&k,    g_k);
        cudaGetSymbolAddress((void**)&v,    g_v);
        cudaGetSymbolAddress((void**)&qh,   g_qh);
        cudaGetSymbolAddress((void**)&kh,   g_kh);
        cudaGetSymbolAddress((void**)&vh,   g_vh);
        cudaGetSymbolAddress((void**)&attn, g_attn);
        cudaFuncSetAttribute(attn_mma, cudaFuncAttributeMaxDynamicSharedMemorySize,
                             ATTN_SMEM_BYTES);
        init_done = true;
    }

    // QKV projections (TF32 mma.sync, double-buffered)
    gemm_mma_tf32<<<dim3(DMODEL / 128, ROWS / 128), 256>>>(x, wq_w, wq_b, q, ROWS, DMODEL, DMODEL);
    gemm_mma_tf32<<<dim3(KVD    / 128, ROWS / 128), 256>>>(x, wk_w, wk_b, k, ROWS, KVD,    DMODEL);
    gemm_mma_tf32<<<dim3(KVD    / 128, ROWS / 128), 256>>>(x, wv_w, wv_b, v, ROWS, KVD,    DMODEL);

    // RoPE + head rearrangement
    {
        size_t totq = (size_t)ROWS * NH  * (DHEAD / 2);
        size_t totk = (size_t)ROWS * NKV * (DHEAD / 2);
        size_t totv = (size_t)ROWS * KVD;
        rope_heads<<<(unsigned)((totq + 255) / 256), 256>>>(q, qh, fcos, fsin, NH);
        rope_heads<<<(unsigned)((totk + 255) / 256), 256>>>(k, kh, fcos, fsin, NKV);
        v_heads  <<<(unsigned)((totv + 255) / 256), 256>>>(v, vh);
    }

    // causal GQA attention (TF32 mma.sync)
    attn_mma<<<dim3(SEQ / 128, NH, BATCH), 256, ATTN_SMEM_BYTES>>>(qh, kh, vh, attn);

    // output projection -> d_out
    gemm_mma_tf32<<<dim3(DMODEL / 128, ROWS / 128), 256>>>(attn, wo_w, wo_b, out, ROWS, DMODEL, DMODEL);
}

// round 11
// speedup vs baseline: 2.8750x; 1.0265x over previous
#include <cuda_runtime.h>
#include <math.h>
#include <stdint.h>

#define BATCH  2
#define SEQ    2048
#define DMODEL 2048
#define NH     16
#define NKV    4
#define DHEAD  128
#define REP    (NH / NKV)
#define ROWS   (BATCH * SEQ)     /* 4096 */
#define KVD    (NKV * DHEAD)     /* 512  */

// ---------------- scratch (static device arrays; no allocation) --------------
__device__ float g_q[(size_t)ROWS * DMODEL];
__device__ float g_k[(size_t)ROWS * KVD];
__device__ float g_v[(size_t)ROWS * KVD];
__device__ float g_qh[(size_t)ROWS * DMODEL];
__device__ float g_kh[(size_t)ROWS * KVD];
__device__ float g_vh[(size_t)ROWS * KVD];
__device__ float g_attn[(size_t)ROWS * DMODEL];

__device__ __forceinline__ uint32_t f2tf32(float x)
{
    uint32_t u;
    asm("cvt.rna.tf32.f32 %0, %1;" : "=r"(u) : "f"(x));
    return u;
}

__device__ __forceinline__ void mma_tf32(float* c, const uint32_t* a, const uint32_t* b)
{
    asm volatile(
        "mma.sync.aligned.m16n8k8.row.col.f32.tf32.tf32.f32 "
        "{%0,%1,%2,%3}, {%4,%5,%6,%7}, {%8,%9}, {%0,%1,%2,%3};"
        : "+f"(c[0]), "+f"(c[1]), "+f"(c[2]), "+f"(c[3])
        : "r"(a[0]), "r"(a[1]), "r"(a[2]), "r"(a[3]),
          "r"(b[0]), "r"(b[1]));
}

// ============================================================================
// TF32 mma.sync GEMM (double-buffered smem):  C = A @ W^T + bias
// CTA 128x128, BK=16, 256 threads (8 warps, 4x2), warp tile 32x64.
// ============================================================================
#define LDW 20   /* smem row stride in words: 16 data + 4 pad */

__global__ __launch_bounds__(256) void gemm_mma_tf32(
    const float* __restrict__ A, const float* __restrict__ W,
    const float* __restrict__ bias, float* __restrict__ C,
    int M, int N, int K)
{
    __shared__ float As[2][128][LDW];
    __shared__ float Ws[2][128][LDW];

    const int tid  = threadIdx.x;
    const int wid  = tid >> 5;
    const int lane = tid & 31;
    const int grp  = lane >> 2;   // 0..7
    const int q    = lane & 3;    // 0..3
    const int wm   = wid & 3;     // warp row   (4 in M)
    const int wn   = wid >> 2;    // warp col   (2 in N)
    const int m0   = blockIdx.y << 7;
    const int n0   = blockIdx.x << 7;

    const int lrow = tid >> 2;          // 0..63 (fill row)
    const int lcol = (tid & 3) << 2;    // 0,4,8,12 (fill col)

    float acc[2][8][4];
#pragma unroll
    for (int mt = 0; mt < 2; ++mt)
#pragma unroll
        for (int nt = 0; nt < 8; ++nt)
#pragma unroll
            for (int j = 0; j < 4; ++j) acc[mt][nt][j] = 0.f;

    const float* Arow0 = A + (size_t)(m0 + lrow) * K + lcol;
    const float* Arow1 = A + (size_t)(m0 + lrow + 64) * K + lcol;
    const float* Wrow0 = W + (size_t)(n0 + lrow) * K + lcol;
    const float* Wrow1 = W + (size_t)(n0 + lrow + 64) * K + lcol;

    const int niter = K >> 4;

    float4 ra0 = *reinterpret_cast<const float4*>(Arow0);
    float4 ra1 = *reinterpret_cast<const float4*>(Arow1);
    float4 rw0 = *reinterpret_cast<const float4*>(Wrow0);
    float4 rw1 = *reinterpret_cast<const float4*>(Wrow1);

    // fill buffer 0
    {
        uint32_t* d;
        d = reinterpret_cast<uint32_t*>(&As[0][lrow][lcol]);
        d[0] = f2tf32(ra0.x); d[1] = f2tf32(ra0.y); d[2] = f2tf32(ra0.z); d[3] = f2tf32(ra0.w);
        d = reinterpret_cast<uint32_t*>(&As[0][lrow + 64][lcol]);
        d[0] = f2tf32(ra1.x); d[1] = f2tf32(ra1.y); d[2] = f2tf32(ra1.z); d[3] = f2tf32(ra1.w);
        d = reinterpret_cast<uint32_t*>(&Ws[0][lrow][lcol]);
        d[0] = f2tf32(rw0.x); d[1] = f2tf32(rw0.y); d[2] = f2tf32(rw0.z); d[3] = f2tf32(rw0.w);
        d = reinterpret_cast<uint32_t*>(&Ws[0][lrow + 64][lcol]);
        d[0] = f2tf32(rw1.x); d[1] = f2tf32(rw1.y); d[2] = f2tf32(rw1.z); d[3] = f2tf32(rw1.w);
    }
    __syncthreads();

    for (int it = 0; it < niter; ++it) {
        const int cur = it & 1;
        if (it + 1 < niter) {
            int ko = (it + 1) << 4;
            ra0 = *reinterpret_cast<const float4*>(Arow0 + ko);
            ra1 = *reinterpret_cast<const float4*>(Arow1 + ko);
            rw0 = *reinterpret_cast<const float4*>(Wrow0 + ko);
            rw1 = *reinterpret_cast<const float4*>(Wrow1 + ko);
        }

#pragma unroll
        for (int kk = 0; kk < 2; ++kk) {
            const int kb = kk << 3;
            uint32_t af[2][4];
#pragma unroll
            for (int mt = 0; mt < 2; ++mt) {
                const uint32_t* base = reinterpret_cast<const uint32_t*>(
                    &As[cur][wm * 32 + mt * 16 + grp][kb + q]);
                af[mt][0] = base[0];
                af[mt][1] = base[8 * LDW];
                af[mt][2] = base[4];
                af[mt][3] = base[8 * LDW + 4];
            }
            uint32_t bf[8][2];
#pragma unroll
            for (int nt = 0; nt < 8; ++nt) {
                const uint32_t* base = reinterpret_cast<const uint32_t*>(
                    &Ws[cur][wn * 64 + nt * 8 + grp][kb + q]);
                bf[nt][0] = base[0];
                bf[nt][1] = base[4];
            }
#pragma unroll
            for (int mt = 0; mt < 2; ++mt)
#pragma unroll
                for (int nt = 0; nt < 8; ++nt)
                    mma_tf32(acc[mt][nt], af[mt], bf[nt]);
        }

        if (it + 1 < niter) {
            const int nxt = cur ^ 1;
            uint32_t* d;
            d = reinterpret_cast<uint32_t*>(&As[nxt][lrow][lcol]);
            d[0] = f2tf32(ra0.x); d[1] = f2tf32(ra0.y); d[2] = f2tf32(ra0.z); d[3] = f2tf32(ra0.w);
            d = reinterpret_cast<uint32_t*>(&As[nxt][lrow + 64][lcol]);
            d[0] = f2tf32(ra1.x); d[1] = f2tf32(ra1.y); d[2] = f2tf32(ra1.z); d[3] = f2tf32(ra1.w);
            d = reinterpret_cast<uint32_t*>(&Ws[nxt][lrow][lcol]);
            d[0] = f2tf32(rw0.x); d[1] = f2tf32(rw0.y); d[2] = f2tf32(rw0.z); d[3] = f2tf32(rw0.w);
            d = reinterpret_cast<uint32_t*>(&Ws[nxt][lrow + 64][lcol]);
            d[0] = f2tf32(rw1.x); d[1] = f2tf32(rw1.y); d[2] = f2tf32(rw1.z); d[3] = f2tf32(rw1.w);
        }
        __syncthreads();
    }

    // epilogue
#pragma unroll
    for (int mt = 0; mt < 2; ++mt) {
        const int m = m0 + wm * 32 + mt * 16 + grp;
#pragma unroll
        for (int nt = 0; nt < 8; ++nt) {
            const int n = n0 + wn * 64 + nt * 8 + 2 * q;
            float2 b2 = *reinterpret_cast<const float2*>(bias + n);
            float2 o0, o1;
            o0.x = acc[mt][nt][0] + b2.x;
            o0.y = acc[mt][nt][1] + b2.y;
            o1.x = acc[mt][nt][2] + b2.x;
            o1.y = acc[mt][nt][3] + b2.y;
            *reinterpret_cast<float2*>(C + (size_t)m * N + n)       = o0;
            *reinterpret_cast<float2*>(C + (size_t)(m + 8) * N + n) = o1;
        }
    }
}

// ---------------- fused RoPE(Q) + RoPE(K) + V-rearrange ----------------------
// Q pairs: [B*S, 16, 64]; K pairs: [B*S, 4, 64]; V float2: [B*S, 4, 64]
#define TOTQ ((size_t)ROWS * NH  * (DHEAD / 2))
#define TOTK ((size_t)ROWS * NKV * (DHEAD / 2))
#define TOTV ((size_t)ROWS * KVD / 2)

__global__ void fused_prep(
    const float* __restrict__ qsrc, const float* __restrict__ ksrc,
    const float* __restrict__ vsrc,
    float* __restrict__ qh, float* __restrict__ kh, float* __restrict__ vh,
    const float* __restrict__ cosp, const float* __restrict__ sinp)
{
    size_t idx = (size_t)blockIdx.x * blockDim.x + threadIdx.x;

    if (idx < TOTQ) {
        int i = (int)(idx & 63);
        int h = (int)((idx >> 6) & (NH - 1));
        size_t row = idx >> 10;             // /(16*64)
        int s = (int)(row & (SEQ - 1));
        int b = (int)(row >> 11);
        float2 t = *reinterpret_cast<const float2*>(qsrc + (row * NH + h) * DHEAD + 2 * i);
        float c  = cosp[s * 64 + i];
        float sn = sinp[s * 64 + i];
        float2 o;
        o.x = t.x * c - t.y * sn;
        o.y = t.x * sn + t.y * c;
        *reinterpret_cast<float2*>(qh + ((size_t)(b * NH + h) * SEQ + s) * DHEAD + 2 * i) = o;
        return;
    }
    idx -= TOTQ;
    if (idx < TOTK) {
        int i = (int)(idx & 63);
        int h = (int)((idx >> 6) & (NKV - 1));
        size_t row = idx >> 8;              // /(4*64)
        int s = (int)(row & (SEQ - 1));
        int b = (int)(row >> 11);
        float2 t = *reinterpret_cast<const float2*>(ksrc + (row * NKV + h) * DHEAD + 2 * i);
        float c  = cosp[s * 64 + i];
        float sn = sinp[s * 64 + i];
        float2 o;
        o.x = t.x * c - t.y * sn;
        o.y = t.x * sn + t.y * c;
        *reinterpret_cast<float2*>(kh + ((size_t)(b * NKV + h) * SEQ + s) * DHEAD + 2 * i) = o;
        return;
    }
    idx -= TOTK;
    if (idx < TOTV) {
        int d2 = (int)(idx & 63);
        int h  = (int)((idx >> 6) & 3);
        size_t row = idx >> 8;
        int s = (int)(row & (SEQ - 1));
        int b = (int)(row >> 11);
        float2 t = *reinterpret_cast<const float2*>(vsrc + row * KVD + h * DHEAD + 2 * d2);
        *reinterpret_cast<float2*>(vh + ((size_t)(b * NKV + h) * SEQ + s) * DHEAD + 2 * d2) = t;
    }
}

// ============================================================================
// Flash attention, TF32 mma.sync, causal, GQA.
// CTA: 256 threads (8 warps), BM=128 (warp = 16 rows), BN=64, DK=128.
// K/V tile kt+1 register-prefetched during compute of tile kt.
// LPT: heavy (large qt) CTAs launched first.
// ============================================================================
#define AQ_LD 132
#define AK_LD 132
#define AV_LD 136
#define AP_LD 68
#define ATTN_SMEM_WORDS (128*AQ_LD + 64*AK_LD + 64*AV_LD + 128*AP_LD)
#define ATTN_SMEM_BYTES (ATTN_SMEM_WORDS * 4)

__global__ __launch_bounds__(256, 1) void attn_mma(
    const float* __restrict__ Q, const float* __restrict__ K,
    const float* __restrict__ V, float* __restrict__ O)
{
    extern __shared__ float sm[];
    float* Qs = sm;                        // [128][AQ_LD] tf32 bits, pre-scaled
    float* Ks = Qs + 128 * AQ_LD;          // [64][AK_LD]  tf32 bits
    float* Vs = Ks + 64 * AK_LD;           // [64][AV_LD]  tf32 bits
    float* Ps = Vs + 64 * AV_LD;           // [128][AP_LD] tf32 bits (per-warp rows)

    const int tid  = threadIdx.x;
    const int wid  = tid >> 5;
    const int lane = tid & 31;
    const int grp  = lane >> 2;   // 0..7
    const int qd   = lane & 3;    // 0..3
    const int qt   = (int)gridDim.x - 1 - (int)blockIdx.x;   // LPT: heavy first
    const int h    = blockIdx.y;
    const int b    = blockIdx.z;
    const int g    = h / REP;
    const int mbase = wid * 16;

    const float* Qp = Q + ((size_t)(b * NH  + h) * SEQ + (size_t)qt * 128) * DHEAD;
    const float* Kp = K + ((size_t)(b * NKV + g) * SEQ) * DHEAD;
    const float* Vp = V + ((size_t)(b * NKV + g) * SEQ) * DHEAD;

    const float scale = 0.08838834764831845f;  // 1/sqrt(128)

    // Load Q tile (128x128), scale + tf32-round, row-major
    for (int idx = tid; idx < 128 * 32; idx += 256) {
        int row = idx >> 5;
        int c4  = (idx & 31) << 2;
        float4 v = *reinterpret_cast<const float4*>(Qp + (size_t)row * DHEAD + c4);
        uint32_t* d = reinterpret_cast<uint32_t*>(Qs + row * AQ_LD + c4);
        d[0] = f2tf32(v.x * scale); d[1] = f2tf32(v.y * scale);
        d[2] = f2tf32(v.z * scale); d[3] = f2tf32(v.w * scale);
    }

    // fill tile 0 (K/V) directly
    for (int idx = tid; idx < 64 * 32; idx += 256) {
        int row = idx >> 5;
        int c4  = (idx & 31) << 2;
        size_t goff = (size_t)row * DHEAD + c4;
        float4 kv = *reinterpret_cast<const float4*>(Kp + goff);
        float4 vv = *reinterpret_cast<const float4*>(Vp + goff);
        uint32_t* dk = reinterpret_cast<uint32_t*>(Ks + row * AK_LD + c4);
        dk[0] = f2tf32(kv.x); dk[1] = f2tf32(kv.y);
        dk[2] = f2tf32(kv.z); dk[3] = f2tf32(kv.w);
        uint32_t* dv = reinterpret_cast<uint32_t*>(Vs + row * AV_LD + c4);
        dv[0] = f2tf32(vv.x); dv[1] = f2tf32(vv.y);
        dv[2] = f2tf32(vv.z); dv[3] = f2tf32(vv.w);
    }

    float o[16][4];
#pragma unroll
    for (int nt = 0; nt < 16; ++nt)
#pragma unroll
        for (int j = 0; j < 4; ++j) o[nt][j] = 0.f;
    float m0r = -INFINITY, m1r = -INFINITY;
    float l0 = 0.f, l1 = 0.f;

    const int row0 = qt * 128 + mbase + grp;
    const int row1 = row0 + 8;
    const int nkt  = 2 * qt + 2;

    float4 pk[8], pv[8];

    for (int kt = 0; kt < nkt; ++kt) {
        __syncthreads();   // tile kt (and Q on kt=0) visible

        // prefetch tile kt+1 into registers (overlaps with all compute below)
        if (kt + 1 < nkt) {
#pragma unroll
            for (int i = 0; i < 8; ++i) {
                int idx = tid + (i << 8);
                int row = idx >> 5;
                int c4  = (idx & 31) << 2;
                size_t goff = ((size_t)(kt + 1) * 64 + row) * DHEAD + c4;
                pk[i] = *reinterpret_cast<const float4*>(Kp + goff);
                pv[i] = *reinterpret_cast<const float4*>(Vp + goff);
            }
        }

        // ---- S = Q K^T : warp computes 16x64, 16 k-steps ----
        float sacc[8][4];
#pragma unroll
        for (int nt = 0; nt < 8; ++nt)
#pragma unroll
            for (int j = 0; j < 4; ++j) sacc[nt][j] = 0.f;

#pragma unroll
        for (int ks = 0; ks < 16; ++ks) {
            uint32_t a[4];
            const uint32_t* abase = reinterpret_cast<const uint32_t*>(
                Qs + (mbase + grp) * AQ_LD + ks * 8 + qd);
            a[0] = abase[0];
            a[1] = abase[8 * AQ_LD];
            a[2] = abase[4];
            a[3] = abase[8 * AQ_LD + 4];
#pragma unroll
            for (int nt = 0; nt < 8; ++nt) {
                uint32_t bb[2];
                const uint32_t* bbase = reinterpret_cast<const uint32_t*>(
                    Ks + (nt * 8 + grp) * AK_LD + ks * 8 + qd);
                bb[0] = bbase[0];
                bb[1] = bbase[4];
                mma_tf32(sacc[nt], a, bb);
            }
        }

        // ---- causal mask (partial tiles only) ----
        if (kt >= 2 * qt) {
            const int colb = kt * 64;
#pragma unroll
            for (int nt = 0; nt < 8; ++nt) {
                int c = colb + nt * 8 + 2 * qd;
                if (c     > row0) sacc[nt][0] = -INFINITY;
                if (c + 1 > row0) sacc[nt][1] = -INFINITY;
                if (c     > row1) sacc[nt][2] = -INFINITY;
                if (c + 1 > row1) sacc[nt][3] = -INFINITY;
            }
        }

        // ---- online softmax (rows row0, row1) ----
        float mt0 = -INFINITY, mt1 = -INFINITY;
#pragma unroll
        for (int nt = 0; nt < 8; ++nt) {
            mt0 = fmaxf(mt0, fmaxf(sacc[nt][0], sacc[nt][1]));
            mt1 = fmaxf(mt1, fmaxf(sacc[nt][2], sacc[nt][3]));
        }
        mt0 = fmaxf(mt0, __shfl_xor_sync(0xffffffffu, mt0, 1));
        mt0 = fmaxf(mt0, __shfl_xor_sync(0xffffffffu, mt0, 2));
        mt1 = fmaxf(mt1, __shfl_xor_sync(0xffffffffu, mt1, 1));
        mt1 = fmaxf(mt1, __shfl_xor_sync(0xffffffffu, mt1, 2));

        float mn0 = fmaxf(m0r, mt0), mn1 = fmaxf(m1r, mt1);
        float al0 = __expf(m0r - mn0), al1 = __expf(m1r - mn1);
        m0r = mn0; m1r = mn1;

        float sum0 = 0.f, sum1 = 0.f;
#pragma unroll
        for (int nt = 0; nt < 8; ++nt) {
            float p0 = __expf(sacc[nt][0] - m0r);
            float p1 = __expf(sacc[nt][1] - m0r);
            float p2 = __expf(sacc[nt][2] - m1r);
            float p3 = __expf(sacc[nt][3] - m1r);
            sum0 += p0 + p1;
            sum1 += p2 + p3;
            uint32_t* d0 = reinterpret_cast<uint32_t*>(
                Ps + (mbase + grp) * AP_LD + nt * 8 + 2 * qd);
            d0[0] = f2tf32(p0); d0[1] = f2tf32(p1);
            uint32_t* d1 = reinterpret_cast<uint32_t*>(
                Ps + (mbase + grp + 8) * AP_LD + nt * 8 + 2 * qd);
            d1[0] = f2tf32(p2); d1[1] = f2tf32(p3);
        }
        sum0 += __shfl_xor_sync(0xffffffffu, sum0, 1);
        sum0 += __shfl_xor_sync(0xffffffffu, sum0, 2);
        sum1 += __shfl_xor_sync(0xffffffffu, sum1, 1);
        sum1 += __shfl_xor_sync(0xffffffffu, sum1, 2);
        l0 = l0 * al0 + sum0;
        l1 = l1 * al1 + sum1;

#pragma unroll
        for (int nt = 0; nt < 16; ++nt) {
            o[nt][0] *= al0; o[nt][1] *= al0;
            o[nt][2] *= al1; o[nt][3] *= al1;
        }

        __syncwarp();   // Ps rows are warp-private; order STS -> LDS within warp

        // ---- O += P V : warp 16x128, 8 k-steps ----
#pragma unroll
        for (int ks = 0; ks < 8; ++ks) {
            uint32_t a[4];
            const uint32_t* abase = reinterpret_cast<const uint32_t*>(
                Ps + (mbase + grp) * AP_LD + ks * 8 + qd);
            a[0] = abase[0];
            a[1] = abase[8 * AP_LD];
            a[2] = abase[4];
            a[3] = abase[8 * AP_LD + 4];
#pragma unroll
            for (int nt = 0; nt < 16; ++nt) {
                uint32_t bb[2];
                const uint32_t* bbase = reinterpret_cast<const uint32_t*>(
                    Vs + (ks * 8 + qd) * AV_LD + nt * 8 + grp);
                bb[0] = bbase[0];
                bb[1] = bbase[4 * AV_LD];
                mma_tf32(o[nt], a, bb);
            }
        }

        __syncthreads();   // all reads of tile kt done

        // store prefetched tile kt+1
        if (kt + 1 < nkt) {
#pragma unroll
            for (int i = 0; i < 8; ++i) {
                int idx = tid + (i << 8);
                int row = idx >> 5;
                int c4  = (idx & 31) << 2;
                uint32_t* dk = reinterpret_cast<uint32_t*>(Ks + row * AK_LD + c4);
                dk[0] = f2tf32(pk[i].x); dk[1] = f2tf32(pk[i].y);
                dk[2] = f2tf32(pk[i].z); dk[3] = f2tf32(pk[i].w);
                uint32_t* dv = reinterpret_cast<uint32_t*>(Vs + row * AV_LD + c4);
                dv[0] = f2tf32(pv[i].x); dv[1] = f2tf32(pv[i].y);
                dv[2] = f2tf32(pv[i].z); dv[3] = f2tf32(pv[i].w);
            }
        }
    }

    // ---- epilogue: normalize, write [B*S, D] at head column block ----
    float inv0 = 1.f / l0, inv1 = 1.f / l1;
    size_t gr0 = ((size_t)b * SEQ + qt * 128 + mbase + grp) * DMODEL + (size_t)h * DHEAD;
    size_t gr1 = gr0 + 8 * DMODEL;
#pragma unroll
    for (int nt = 0; nt < 16; ++nt) {
        int c = nt * 8 + 2 * qd;
        float2 w0, w1;
        w0.x = o[nt][0] * inv0; w0.y = o[nt][1] * inv0;
        w1.x = o[nt][2] * inv1; w1.y = o[nt][3] * inv1;
        *reinterpret_cast<float2*>(O + gr0 + c) = w0;
        *reinterpret_cast<float2*>(O + gr1 + c) = w1;
    }
}

// ---------------- launch ------------------------------------------------------
extern "C" void kernel_launch(void* const* d_in, const int* in_sizes, int n_in,
                              void* d_out, int out_size)
{
    const float* x    = (const float*)d_in[0];
    const float* fcos = (const float*)d_in[1];
    const float* fsin = (const float*)d_in[2];
    const float* wq_w = (const float*)d_in[3];
    const float* wq_b = (const float*)d_in[4];
    const float* wk_w = (const float*)d_in[5];
    const float* wk_b = (const float*)d_in[6];
    const float* wv_w = (const float*)d_in[7];
    const float* wv_b = (const float*)d_in[8];
    const float* wo_w = (const float*)d_in[9];
    const float* wo_b = (const float*)d_in[10];
    float* out = (float*)d_out;

    static float *q = nullptr, *k, *v, *qh, *kh, *vh, *attn;
    static bool init_done = false;
    if (!init_done) {
        cudaGetSymbolAddress((void**)&q,    g_q);
        cudaGetSymbolAddress((void**)&k,    g_k);
        cudaGetSymbolAddress((void**)&v,    g_v);
        cudaGetSymbolAddress((void**)&qh,   g_qh);
        cudaGetSymbolAddress((void**)&kh,   g_kh);
        cudaGetSymbolAddress((void**)&vh,   g_vh);
        cudaGetSymbolAddress((void**)&attn, g_attn);
        cudaFuncSetAttribute(attn_mma, cudaFuncAttributeMaxDynamicSharedMemorySize,
                             ATTN_SMEM_BYTES);
        init_done = true;
    }

    // QKV projections (TF32 mma.sync, double-buffered)
    gemm_mma_tf32<<<dim3(DMODEL / 128, ROWS / 128), 256>>>(x, wq_w, wq_b, q, ROWS, DMODEL, DMODEL);
    gemm_mma_tf32<<<dim3(KVD    / 128, ROWS / 128), 256>>>(x, wk_w, wk_b, k, ROWS, KVD,    DMODEL);
    gemm_mma_tf32<<<dim3(KVD    / 128, ROWS / 128), 256>>>(x, wv_w, wv_b, v, ROWS, KVD,    DMODEL);

    // fused RoPE + head rearrangement (one launch)
    {
        size_t tot = TOTQ + TOTK + TOTV;
        fused_prep<<<(unsigned)((tot + 255) / 256), 256>>>(q, k, v, qh, kh, vh, fcos, fsin);
    }

    // causal GQA attention (TF32 mma.sync, prefetch + LPT)
    attn_mma<<<dim3(SEQ / 128, NH, BATCH), 256, ATTN_SMEM_BYTES>>>(qh, kh, vh, attn);

    // output projection -> d_out   (launch #5 -> gets profiled by ncu -s 5)
    gemm_mma_tf32<<<dim3(DMODEL / 128, ROWS / 128), 256>>>(attn, wo_w, wo_b, out, ROWS, DMODEL, DMODEL);
}